// round 2
// baseline (speedup 1.0000x reference)
#include <cuda_runtime.h>

#define T_DIM 1024
#define F_DIM 256
#define UNITS 32
#define AW    64
#define HALF  32
#define B_DIM 4
#define NROWS (B_DIM * T_DIM)

// Scratch: projected q (bh folded), k, and normalized band weights a.
__device__ float g_q[NROWS * UNITS];
__device__ float g_k[NROWS * UNITS];
__device__ float g_a[NROWS * AW];

__device__ __forceinline__ float tanh_approx(float x) {
    float y;
    asm("tanh.approx.f32 %0, %1;" : "=f"(y) : "f"(x));
    return y;
}

// ---------------------------------------------------------------------------
// Kernel 1: q = x@Wt + bh, k = x@Wx. 256 blocks x 256 thr, 16 rows/block.
// float4 smem broadcasts of x + 4 coalesced W loads per iter -> FMA-bound.
// ---------------------------------------------------------------------------
__global__ void __launch_bounds__(256) qk_kernel(
    const float* __restrict__ x,
    const float* __restrict__ Wt,
    const float* __restrict__ Wx,
    const float* __restrict__ bh)
{
    __shared__ float xs[16 * F_DIM];

    const int tid = threadIdx.x;
    const int r0  = blockIdx.x * 16;

    const float4* xg  = reinterpret_cast<const float4*>(x) + (size_t)r0 * (F_DIM / 4);
    float4*       xs4 = reinterpret_cast<float4*>(xs);
    #pragma unroll
    for (int i = 0; i < 4; i++)
        xs4[tid + i * 256] = xg[tid + i * 256];
    __syncthreads();

    const int  wid  = tid >> 5;
    const int  lane = tid & 31;
    const bool is_q = (wid < 4);
    const float* __restrict__ W = is_q ? Wt : Wx;
    const int  rb   = (wid & 3) * 4;   // 4 rows per warp

    float acc0 = 0.f, acc1 = 0.f, acc2 = 0.f, acc3 = 0.f;
    const float4* x0 = xs4 + (rb + 0) * (F_DIM / 4);
    const float4* x1 = xs4 + (rb + 1) * (F_DIM / 4);
    const float4* x2 = xs4 + (rb + 2) * (F_DIM / 4);
    const float4* x3 = xs4 + (rb + 3) * (F_DIM / 4);

    #pragma unroll 4
    for (int f4 = 0; f4 < F_DIM / 4; f4++) {
        const float w0 = W[(f4 * 4 + 0) * UNITS + lane];
        const float w1 = W[(f4 * 4 + 1) * UNITS + lane];
        const float w2 = W[(f4 * 4 + 2) * UNITS + lane];
        const float w3 = W[(f4 * 4 + 3) * UNITS + lane];
        const float4 a0 = x0[f4], a1 = x1[f4], a2 = x2[f4], a3 = x3[f4];
        acc0 += a0.x * w0 + a0.y * w1 + a0.z * w2 + a0.w * w3;
        acc1 += a1.x * w0 + a1.y * w1 + a1.z * w2 + a1.w * w3;
        acc2 += a2.x * w0 + a2.y * w1 + a2.z * w2 + a2.w * w3;
        acc3 += a3.x * w0 + a3.y * w1 + a3.z * w2 + a3.w * w3;
    }

    const float bias = is_q ? bh[lane] : 0.f;
    float* __restrict__ G = is_q ? g_q : g_k;
    G[(size_t)(r0 + rb + 0) * UNITS + lane] = acc0 + bias;
    G[(size_t)(r0 + rb + 1) * UNITS + lane] = acc1 + bias;
    G[(size_t)(r0 + rb + 2) * UNITS + lane] = acc2 + bias;
    G[(size_t)(r0 + rb + 3) * UNITS + lane] = acc3 + bias;
}

// ---------------------------------------------------------------------------
// Kernel 2: band logits + softmax -> g_a. Block = (b, 16 t), grid (64, B).
// a[t][j], j in [0,64), s = t-32+j; masked (0) when s outside [0,T).
// ---------------------------------------------------------------------------
__global__ void __launch_bounds__(256) weights_kernel(
    const float* __restrict__ Wa,
    const float* __restrict__ ba)
{
    const int b  = blockIdx.y;
    const int t0 = blockIdx.x * 16;
    const int sbase = t0 - HALF;                 // may be negative
    const int SR = 16 + AW - 1;                  // 79 staged k rows

    __shared__ float ks[79 * 33];                // pad 33 -> conflict-free
    __shared__ float qs[16 * UNITS];
    __shared__ float was[UNITS];
    __shared__ float es[16 * AW];

    const int tid = threadIdx.x;

    for (int idx = tid; idx < SR * UNITS; idx += 256) {
        const int srel = idx >> 5, u = idx & 31;
        int s = sbase + srel;
        s = min(max(s, 0), T_DIM - 1);           // masked later; keep in-bounds
        ks[srel * 33 + u] = g_k[(size_t)(b * T_DIM + s) * UNITS + u];
    }
    for (int idx = tid; idx < 16 * UNITS; idx += 256)
        qs[idx] = g_q[(size_t)(b * T_DIM + t0) * UNITS + idx];
    if (tid < UNITS) was[tid] = Wa[tid];
    __syncthreads();

    const float bav = ba[0];

    #pragma unroll
    for (int l = 0; l < 4; l++) {
        const int idx = tid + l * 256;           // 1024 logits
        const int tl  = idx >> 6;
        const int j   = idx & 63;
        const int s   = t0 + tl - HALF + j;
        float e = -1e30f;
        if (s >= 0 && s < T_DIM) {
            const int srel = tl + j;
            float acc = 0.f;
            #pragma unroll
            for (int u = 0; u < UNITS; u++)
                acc += was[u] * tanh_approx(qs[tl * UNITS + u] + ks[srel * 33 + u]);
            e = acc + bav;
        }
        es[tl * AW + j] = e;
    }
    __syncthreads();

    const int wid = tid >> 5, lane = tid & 31;
    #pragma unroll
    for (int k = 0; k < 2; k++) {
        const int tl = wid * 2 + k;
        const float e0 = es[tl * AW + lane];
        const float e1 = es[tl * AW + lane + 32];
        float m = fmaxf(e0, e1);
        #pragma unroll
        for (int o = 16; o; o >>= 1)
            m = fmaxf(m, __shfl_xor_sync(0xffffffffu, m, o));
        const float p0 = __expf(e0 - m);
        const float p1 = __expf(e1 - m);
        float sum = p0 + p1;
        #pragma unroll
        for (int o = 16; o; o >>= 1)
            sum += __shfl_xor_sync(0xffffffffu, sum, o);
        const float inv = 1.f / sum;
        const size_t row = (size_t)(b * T_DIM + t0 + tl) * AW;
        g_a[row + lane]      = p0 * inv;
        g_a[row + lane + 32] = p1 * inv;
    }
}

// ---------------------------------------------------------------------------
// Kernel 3: v = banded a @ x. Block = (b, 32 t, 128 f), grid (32, B, 2).
// Thread owns 4 consecutive t + one float4 f-col; slides 67-row window,
// loads each x float4 once, applies to 4 accumulators (x reuse x4).
// ---------------------------------------------------------------------------
__global__ void __launch_bounds__(256) out_kernel(
    const float* __restrict__ x,
    float* __restrict__ out)
{
    const int b   = blockIdx.y;
    const int t0  = blockIdx.x * 32;
    const int fb4 = blockIdx.z * 32;             // float4 units (64 per row)

    __shared__ float as[32 * AW];                // 8KB of weights
    const int tid = threadIdx.x;
    for (int idx = tid; idx < 32 * AW; idx += 256)
        as[idx] = g_a[(size_t)(b * T_DIM + t0) * AW + idx];
    __syncthreads();

    const int tg    = tid >> 5;                  // 8 groups of 4 t
    const int f4    = tid & 31;
    const int tbase = t0 + tg * 4;

    const float4* __restrict__ xg =
        reinterpret_cast<const float4*>(x) + (size_t)b * T_DIM * (F_DIM / 4);

    float4 acc[4];
    #pragma unroll
    for (int r = 0; r < 4; r++) acc[r] = make_float4(0.f, 0.f, 0.f, 0.f);

    const float* aw = as + (tg * 4) * AW;

    #pragma unroll 2
    for (int i = 0; i < AW + 3; i++) {           // union window: 67 rows
        int s = tbase - HALF + i;
        s = min(max(s, 0), T_DIM - 1);           // weight is 0 when invalid
        const float4 xv = __ldg(&xg[(size_t)s * (F_DIM / 4) + fb4 + f4]);
        #pragma unroll
        for (int r = 0; r < 4; r++) {
            const int j = i - r;
            const float w = ((unsigned)j < (unsigned)AW) ? aw[r * AW + j] : 0.f;
            acc[r].x += w * xv.x;
            acc[r].y += w * xv.y;
            acc[r].z += w * xv.z;
            acc[r].w += w * xv.w;
        }
    }

    float4* __restrict__ og =
        reinterpret_cast<float4*>(out) + (size_t)b * T_DIM * (F_DIM / 4);
    #pragma unroll
    for (int r = 0; r < 4; r++)
        og[(size_t)(tbase + r) * (F_DIM / 4) + fb4 + f4] = acc[r];
}

extern "C" void kernel_launch(void* const* d_in, const int* in_sizes, int n_in,
                              void* d_out, int out_size)
{
    const float* x  = (const float*)d_in[0];
    const float* Wt = (const float*)d_in[1];
    const float* Wx = (const float*)d_in[2];
    const float* bh = (const float*)d_in[3];
    const float* Wa = (const float*)d_in[4];
    const float* ba = (const float*)d_in[5];
    float* out = (float*)d_out;

    qk_kernel<<<NROWS / 16, 256>>>(x, Wt, Wx, bh);
    weights_kernel<<<dim3(T_DIM / 16, B_DIM), 256>>>(Wa, ba);
    out_kernel<<<dim3(T_DIM / 32, B_DIM, 2), 256>>>(x, out);
}

// round 3
// speedup vs baseline: 1.3540x; 1.3540x over previous
#include <cuda_runtime.h>

#define T_DIM 1024
#define F_DIM 256
#define UNITS 32
#define AW    64
#define HALF  32
#define B_DIM 4
#define NROWS (B_DIM * T_DIM)

__device__ float g_q[NROWS * UNITS];
__device__ float g_k[NROWS * UNITS];
__device__ float g_a[NROWS * AW];

__device__ __forceinline__ float tanh_approx(float x) {
    float y;
    asm("tanh.approx.f32 %0, %1;" : "=f"(y) : "f"(x));
    return y;
}

// ---------------------------------------------------------------------------
// Kernel 1: q = x@Wt + bh, k = x@Wx.
// 512 blocks x 256 thr, 8 rows/block. Warps 0-3: q (2 rows each), 4-7: k.
// ---------------------------------------------------------------------------
__global__ void __launch_bounds__(256) qk_kernel(
    const float* __restrict__ x,
    const float* __restrict__ Wt,
    const float* __restrict__ Wx,
    const float* __restrict__ bh)
{
    __shared__ float4 xs4[8 * (F_DIM / 4)];   // 8 rows = 8KB

    const int tid = threadIdx.x;
    const int r0  = blockIdx.x * 8;

    const float4* xg = reinterpret_cast<const float4*>(x) + (size_t)r0 * (F_DIM / 4);
    xs4[tid]       = xg[tid];
    xs4[tid + 256] = xg[tid + 256];
    __syncthreads();

    const int  wid  = tid >> 5;
    const int  lane = tid & 31;
    const bool is_q = (wid < 4);
    const float* __restrict__ W = is_q ? Wt : Wx;
    const int  rb   = (wid & 3) * 2;   // 2 rows per warp

    float acc0 = 0.f, acc1 = 0.f;
    const float4* x0 = xs4 + (rb + 0) * (F_DIM / 4);
    const float4* x1 = xs4 + (rb + 1) * (F_DIM / 4);

    #pragma unroll 4
    for (int f4 = 0; f4 < F_DIM / 4; f4++) {
        const float w0 = W[(f4 * 4 + 0) * UNITS + lane];
        const float w1 = W[(f4 * 4 + 1) * UNITS + lane];
        const float w2 = W[(f4 * 4 + 2) * UNITS + lane];
        const float w3 = W[(f4 * 4 + 3) * UNITS + lane];
        const float4 v0 = x0[f4];
        const float4 v1 = x1[f4];
        acc0 += v0.x * w0 + v0.y * w1 + v0.z * w2 + v0.w * w3;
        acc1 += v1.x * w0 + v1.y * w1 + v1.z * w2 + v1.w * w3;
    }

    const float bias = is_q ? bh[lane] : 0.f;
    float* __restrict__ G = is_q ? g_q : g_k;
    G[(size_t)(r0 + rb + 0) * UNITS + lane] = acc0 + bias;
    G[(size_t)(r0 + rb + 1) * UNITS + lane] = acc1 + bias;
}

// ---------------------------------------------------------------------------
// Kernel 2: band logits + softmax -> g_a. 8 t per block, grid (128, B).
// ---------------------------------------------------------------------------
__global__ void __launch_bounds__(256) weights_kernel(
    const float* __restrict__ Wa,
    const float* __restrict__ ba)
{
    const int b  = blockIdx.y;
    const int t0 = blockIdx.x * 8;
    const int sbase = t0 - HALF;
    const int SR = 8 + AW - 1;                   // 71 staged k rows

    __shared__ float ks[71 * 33];
    __shared__ float qs[8 * UNITS];
    __shared__ float was[UNITS];
    __shared__ float es[8 * AW];

    const int tid = threadIdx.x;

    for (int idx = tid; idx < SR * UNITS; idx += 256) {
        const int srel = idx >> 5, u = idx & 31;
        int s = sbase + srel;
        s = min(max(s, 0), T_DIM - 1);
        ks[srel * 33 + u] = g_k[(size_t)(b * T_DIM + s) * UNITS + u];
    }
    if (tid < 8 * UNITS)
        qs[tid] = g_q[(size_t)(b * T_DIM + t0) * UNITS + tid];
    if (tid < UNITS) was[tid] = Wa[tid];
    __syncthreads();

    const float bav = ba[0];

    #pragma unroll
    for (int l = 0; l < 2; l++) {
        const int idx = tid + l * 256;           // 512 logits
        const int tl  = idx >> 6;
        const int j   = idx & 63;
        const int s   = t0 + tl - HALF + j;
        float e = -1e30f;
        if (s >= 0 && s < T_DIM) {
            const int srel = tl + j;
            float acc = 0.f;
            #pragma unroll
            for (int u = 0; u < UNITS; u++)
                acc += was[u] * tanh_approx(qs[tl * UNITS + u] + ks[srel * 33 + u]);
            e = acc + bav;
        }
        es[tl * AW + j] = e;
    }
    __syncthreads();

    const int wid = tid >> 5, lane = tid & 31;   // warp wid -> t row wid
    {
        const float e0 = es[wid * AW + lane];
        const float e1 = es[wid * AW + lane + 32];
        float m = fmaxf(e0, e1);
        #pragma unroll
        for (int o = 16; o; o >>= 1)
            m = fmaxf(m, __shfl_xor_sync(0xffffffffu, m, o));
        const float p0 = __expf(e0 - m);
        const float p1 = __expf(e1 - m);
        float sum = p0 + p1;
        #pragma unroll
        for (int o = 16; o; o >>= 1)
            sum += __shfl_xor_sync(0xffffffffu, sum, o);
        const float inv = 1.f / sum;
        const size_t row = (size_t)(b * T_DIM + t0 + wid) * AW;
        g_a[row + lane]      = p0 * inv;
        g_a[row + lane + 32] = p1 * inv;
    }
}

// ---------------------------------------------------------------------------
// Kernel 3: v = banded a @ x. Thread = (2 consecutive t, 1 float4 f-col).
// grid (64, B, 2), block 256: 16 t x 32 f4 per block. 512 blocks.
// ---------------------------------------------------------------------------
__global__ void __launch_bounds__(256) out_kernel(
    const float* __restrict__ x,
    float* __restrict__ out)
{
    const int b   = blockIdx.y;
    const int t0  = blockIdx.x * 16;
    const int fb4 = blockIdx.z * 32;

    __shared__ float as[16 * AW];                // 4KB weights
    const int tid = threadIdx.x;
    #pragma unroll
    for (int l = 0; l < 4; l++)
        as[tid + l * 256] = g_a[(size_t)(b * T_DIM + t0) * AW + tid + l * 256];
    __syncthreads();

    const int tg    = tid >> 5;                  // 8 groups of 2 t
    const int f4    = fb4 + (tid & 31);
    const int tbase = t0 + tg * 2;

    const float4* __restrict__ xg =
        reinterpret_cast<const float4*>(x) + (size_t)b * T_DIM * (F_DIM / 4);
    const float* aw0 = as + (tg * 2 + 0) * AW;
    const float* aw1 = as + (tg * 2 + 1) * AW;

    float4 acc0 = make_float4(0.f, 0.f, 0.f, 0.f);
    float4 acc1 = make_float4(0.f, 0.f, 0.f, 0.f);

    #pragma unroll 4
    for (int i = 0; i < AW + 1; i++) {           // union window: 65 rows
        int s = tbase - HALF + i;
        s = min(max(s, 0), T_DIM - 1);           // invalid s has weight 0
        const float4 xv = __ldg(&xg[(size_t)s * (F_DIM / 4) + f4]);
        const float w0 = (i < AW) ? aw0[i] : 0.f;
        const float w1 = (i > 0)  ? aw1[i - 1] : 0.f;
        acc0.x += w0 * xv.x;  acc0.y += w0 * xv.y;
        acc0.z += w0 * xv.z;  acc0.w += w0 * xv.w;
        acc1.x += w1 * xv.x;  acc1.y += w1 * xv.y;
        acc1.z += w1 * xv.z;  acc1.w += w1 * xv.w;
    }

    float4* __restrict__ og =
        reinterpret_cast<float4*>(out) + (size_t)b * T_DIM * (F_DIM / 4);
    og[(size_t)(tbase + 0) * (F_DIM / 4) + f4] = acc0;
    og[(size_t)(tbase + 1) * (F_DIM / 4) + f4] = acc1;
}

extern "C" void kernel_launch(void* const* d_in, const int* in_sizes, int n_in,
                              void* d_out, int out_size)
{
    const float* x  = (const float*)d_in[0];
    const float* Wt = (const float*)d_in[1];
    const float* Wx = (const float*)d_in[2];
    const float* bh = (const float*)d_in[3];
    const float* Wa = (const float*)d_in[4];
    const float* ba = (const float*)d_in[5];
    float* out = (float*)d_out;

    qk_kernel<<<NROWS / 8, 256>>>(x, Wt, Wx, bh);
    weights_kernel<<<dim3(T_DIM / 8, B_DIM), 256>>>(Wa, ba);
    out_kernel<<<dim3(T_DIM / 16, B_DIM, 2), 256>>>(x, out);
}